// round 1
// baseline (speedup 1.0000x reference)
#include <cuda_runtime.h>
#include <math.h>
#include <stdint.h>

#define HEADS   16
#define DH      64
#define BLK     16
#define SEQ     2048
#define NB      128          // SEQ / BLK
#define BATCH   2
#define DIM     1024
#define N3      3072
#define MROWS   (BATCH * SEQ)   // 4096

// Scratch (device globals: allowed; no allocations anywhere)
__device__ float g_qkv[(size_t)MROWS * N3];   // 4096 x 3072
__device__ float g_att[(size_t)MROWS * DIM];  // 4096 x 1024

// ---------------------------------------------------------------------------
// SGEMM: C[M,N] = A[M,K] @ B[K,N] (+ bias), all row-major, fp32.
// 128x128 tile, BK=8, 256 threads, 8x8 microtile. M,N,K multiples of 128/8.
// ---------------------------------------------------------------------------
template<bool BIAS>
__global__ void __launch_bounds__(256)
sgemm128(const float* __restrict__ A, const float* __restrict__ B,
         const float* __restrict__ bias, float* __restrict__ C,
         int M, int N, int K)
{
    constexpr int BM = 128, BN = 128, BK = 8, TM = 8, TN = 8;
    __shared__ float As[BK * BM];   // transposed: As[k*BM + m]
    __shared__ float Bs[BK * BN];

    const int tid  = threadIdx.x;
    const int tcol = tid % (BN / TN);    // 0..15
    const int trow = tid / (BN / TN);    // 0..15

    const float* Ab = A + (size_t)blockIdx.y * BM * K;
    const float* Bb = B + (size_t)blockIdx.x * BN;

    float acc[TM * TN];
    #pragma unroll
    for (int i = 0; i < TM * TN; i++) acc[i] = 0.0f;

    const int arow   = tid >> 1;          // 0..127
    const int acol   = (tid & 1) * 4;     // 0 or 4
    const int brow_l = tid >> 5;          // 0..7
    const int bcol_l = (tid & 31) * 4;    // 0..124

    for (int k0 = 0; k0 < K; k0 += BK) {
        float4 a4 = *(const float4*)(Ab + (size_t)arow * K + k0 + acol);
        As[(acol + 0) * BM + arow] = a4.x;
        As[(acol + 1) * BM + arow] = a4.y;
        As[(acol + 2) * BM + arow] = a4.z;
        As[(acol + 3) * BM + arow] = a4.w;
        *(float4*)(Bs + brow_l * BN + bcol_l) =
            *(const float4*)(Bb + (size_t)(k0 + brow_l) * N + bcol_l);
        __syncthreads();

        #pragma unroll
        for (int k = 0; k < BK; k++) {
            float rm[TM], rn[TN];
            #pragma unroll
            for (int i = 0; i < TM; i++) rm[i] = As[k * BM + trow * TM + i];
            #pragma unroll
            for (int j = 0; j < TN; j++) rn[j] = Bs[k * BN + tcol * TN + j];
            #pragma unroll
            for (int i = 0; i < TM; i++)
                #pragma unroll
                for (int j = 0; j < TN; j++)
                    acc[i * TN + j] = fmaf(rm[i], rn[j], acc[i * TN + j]);
        }
        __syncthreads();
    }

    // Write back (two float4 per row of microtile)
    #pragma unroll
    for (int i = 0; i < TM; i++) {
        int row = blockIdx.y * BM + trow * TM + i;
        int col = blockIdx.x * BN + tcol * TN;
        float* cp = C + (size_t)row * N + col;
        #pragma unroll
        for (int j4 = 0; j4 < TN; j4 += 4) {
            float4 v;
            v.x = acc[i * TN + j4 + 0];
            v.y = acc[i * TN + j4 + 1];
            v.z = acc[i * TN + j4 + 2];
            v.w = acc[i * TN + j4 + 3];
            if (BIAS) {
                v.x += bias[col + j4 + 0];
                v.y += bias[col + j4 + 1];
                v.z += bias[col + j4 + 2];
                v.w += bias[col + j4 + 3];
            }
            *(float4*)(cp + j4) = v;
        }
    }
}

// ---------------------------------------------------------------------------
// Block-sparse attention. One CTA per (query block qb, head h, batch bz).
// 256 threads. Online (flash-style) softmax over allowed 16x16 key blocks.
// qkv layout: [MROWS, 3072] with Q at col h*64, K at 1024+h*64, V at 2048+h*64.
// ---------------------------------------------------------------------------
__global__ void __launch_bounds__(256)
attn_kernel(const float* __restrict__ qkv, const void* __restrict__ layout,
            float* __restrict__ att)
{
    const int qb = blockIdx.x;
    const int h  = blockIdx.y;
    const int bz = blockIdx.z;
    const int tid = threadIdx.x;

    __shared__ float qs[16 * 65];   // padded stride 65
    __shared__ float ks[16 * 65];   // padded stride 65
    __shared__ float vs[16 * 64];
    __shared__ float ps[16 * 17];   // scores / probs, padded
    __shared__ float m_s[16], l_s[16], alpha_s[16];

    // layout encoding detection: byte-packed iff word 32 == 0x0101 (structural)
    const int probe = __ldg(&((const int*)layout)[32]);
    const bool lay_u8 = (probe == 257);
    const unsigned char* lay8 = (const unsigned char*)layout;
    const int* lay32 = (const int*)layout;

    const float scale = 0.125f;  // 64^-0.5

    // Load Q tile (pre-scaled). 256 threads x 4 floats = 1024.
    {
        int idx = tid * 4;
        int i = idx >> 6, d = idx & 63;
        int grow = qb * 16 + i;
        const float* qp = qkv + ((size_t)(bz * SEQ) + grow) * N3 + h * 64 + d;
        float4 q4 = *(const float4*)qp;
        qs[i * 65 + d + 0] = q4.x * scale;
        qs[i * 65 + d + 1] = q4.y * scale;
        qs[i * 65 + d + 2] = q4.z * scale;
        qs[i * 65 + d + 3] = q4.w * scale;
    }
    if (tid < 16) { m_s[tid] = -INFINITY; l_s[tid] = 0.0f; }

    const int orow = tid >> 4;        // 0..15
    const int ocol = (tid & 15) * 4;  // 0..60
    float acc0 = 0.f, acc1 = 0.f, acc2 = 0.f, acc3 = 0.f;

    for (int kb = 0; kb <= qb; kb++) {
        bool allowed = lay_u8 ? (lay8[qb * NB + kb] != 0)
                              : (lay32[qb * NB + kb] != 0);
        if (!allowed) continue;

        __syncthreads();  // protect ks/vs/ps from previous iteration readers

        // Load K and V 16x64 tiles
        {
            int idx = tid * 4;
            int i = idx >> 6, d = idx & 63;
            int grow = kb * 16 + i;
            size_t base = ((size_t)(bz * SEQ) + grow) * N3 + h * 64 + d;
            float4 k4 = *(const float4*)(qkv + base + 1024);
            ks[i * 65 + d + 0] = k4.x;
            ks[i * 65 + d + 1] = k4.y;
            ks[i * 65 + d + 2] = k4.z;
            ks[i * 65 + d + 3] = k4.w;
            *(float4*)(vs + i * 64 + d) = *(const float4*)(qkv + base + 2048);
        }
        __syncthreads();

        // Scores S[i][j] = (scaled q_i) . k_j
        {
            int i = tid >> 4, j = tid & 15;
            float s = 0.0f;
            #pragma unroll
            for (int d = 0; d < 64; d++)
                s = fmaf(qs[i * 65 + d], ks[j * 65 + d], s);
            if (kb == qb && j > i) s = -1e30f;  // causal within diagonal block
            ps[i * 17 + j] = s;
        }
        __syncthreads();

        // Online softmax state update (one thread per row)
        if (tid < 16) {
            int i = tid;
            float mo = m_s[i];
            float mx = mo;
            #pragma unroll
            for (int j = 0; j < 16; j++) mx = fmaxf(mx, ps[i * 17 + j]);
            float al = __expf(mo - mx);
            float sum = 0.0f;
            #pragma unroll
            for (int j = 0; j < 16; j++) {
                float e = __expf(ps[i * 17 + j] - mx);
                ps[i * 17 + j] = e;
                sum += e;
            }
            l_s[i] = l_s[i] * al + sum;
            m_s[i] = mx;
            alpha_s[i] = al;
        }
        __syncthreads();

        // O update: acc = acc*alpha + P[row,:] @ V[:, col..col+3]
        {
            float al = alpha_s[orow];
            acc0 *= al; acc1 *= al; acc2 *= al; acc3 *= al;
            #pragma unroll
            for (int j = 0; j < 16; j++) {
                float p = ps[orow * 17 + j];
                const float* vr = vs + j * 64 + ocol;
                acc0 = fmaf(p, vr[0], acc0);
                acc1 = fmaf(p, vr[1], acc1);
                acc2 = fmaf(p, vr[2], acc2);
                acc3 = fmaf(p, vr[3], acc3);
            }
        }
    }

    __syncthreads();
    {
        float inv = 1.0f / l_s[orow];
        int grow = qb * 16 + orow;
        float4 o4;
        o4.x = acc0 * inv; o4.y = acc1 * inv; o4.z = acc2 * inv; o4.w = acc3 * inv;
        *(float4*)(att + ((size_t)(bz * SEQ) + grow) * DIM + h * 64 + ocol) = o4;
    }
}

// ---------------------------------------------------------------------------
extern "C" void kernel_launch(void* const* d_in, const int* in_sizes, int n_in,
                              void* d_out, int out_size)
{
    const float* x      = (const float*)d_in[0];
    const float* w_qkv  = (const float*)d_in[1];
    const float* w_out  = (const float*)d_in[2];
    const float* b_out  = (const float*)d_in[3];
    const void*  layout = d_in[4];
    float* out = (float*)d_out;

    void* p;
    cudaGetSymbolAddress(&p, g_qkv);
    float* qkv = (float*)p;
    cudaGetSymbolAddress(&p, g_att);
    float* att = (float*)p;

    // 1) QKV projection: [4096,1024] @ [1024,3072]
    sgemm128<false><<<dim3(N3 / 128, MROWS / 128), 256>>>(
        x, w_qkv, nullptr, qkv, MROWS, N3, DIM);

    // 2) Block-sparse attention
    attn_kernel<<<dim3(NB, HEADS, BATCH), 256>>>(qkv, layout, att);

    // 3) Output projection + bias: [4096,1024] @ [1024,1024]
    sgemm128<true><<<dim3(DIM / 128, MROWS / 128), 256>>>(
        att, w_out, b_out, out, MROWS, DIM, DIM);
}

// round 3
// speedup vs baseline: 1.5590x; 1.5590x over previous
#include <cuda_runtime.h>
#include <math.h>
#include <stdint.h>

#define HEADS   16
#define DH      64
#define BLK     16
#define SEQ     2048
#define NB      128
#define BATCH   2
#define DIM     1024
#define N3      3072
#define MROWS   (BATCH * SEQ)   // 4096

// ---------------------------------------------------------------------------
// Scratch (device globals — no allocations anywhere)
// ---------------------------------------------------------------------------
__device__ float g_qkv[(size_t)MROWS * N3];    // 4096 x 3072
__device__ float g_att[(size_t)MROWS * DIM];   // 4096 x 1024
__device__ float g_wqkvT[(size_t)N3 * DIM];    // 3072 x 1024 (K-major, tf32-rounded)
__device__ float g_woutT[(size_t)DIM * DIM];   // 1024 x 1024

__device__ __forceinline__ float to_tf32(float x) {
    uint32_t u;
    asm("cvt.rna.tf32.f32 %0, %1;" : "=r"(u) : "f"(x));
    return __uint_as_float(u);
}

// mma.sync m16n8k8 tf32: D = A*B + D  (fp32 accum)
__device__ __forceinline__ void mma_tf32(float* c, const uint32_t* a, const uint32_t* b) {
    asm volatile(
        "mma.sync.aligned.m16n8k8.row.col.f32.tf32.tf32.f32 "
        "{%0,%1,%2,%3}, {%4,%5,%6,%7}, {%8,%9}, {%0,%1,%2,%3};"
        : "+f"(c[0]), "+f"(c[1]), "+f"(c[2]), "+f"(c[3])
        : "r"(a[0]), "r"(a[1]), "r"(a[2]), "r"(a[3]), "r"(b[0]), "r"(b[1]));
}

// ---------------------------------------------------------------------------
// Transpose + tf32 round: dst[C x R] = tf32(src[R x C])^T
// ---------------------------------------------------------------------------
__global__ void __launch_bounds__(256)
transpose_tf32(const float* __restrict__ src, float* __restrict__ dst, int R, int C)
{
    __shared__ float t[32][33];
    int c0 = blockIdx.x * 32, r0 = blockIdx.y * 32;
    int x = threadIdx.x, y = threadIdx.y;  // block (32, 8)
    #pragma unroll
    for (int i = 0; i < 32; i += 8)
        t[y + i][x] = to_tf32(src[(size_t)(r0 + y + i) * C + c0 + x]);
    __syncthreads();
    #pragma unroll
    for (int i = 0; i < 32; i += 8)
        dst[(size_t)(c0 + y + i) * R + r0 + x] = t[x][y + i];
}

// ---------------------------------------------------------------------------
// mma.sync tf32 GEMM: C[M,N] = A[M,K] @ Bt[N,K]^T (+bias). K multiple of 32.
// 128x128 CTA tile, BK=32, 256 threads = 8 warps; warp tile 64x32.
// SMEM stored in FRAGMENT ORDER so fragment fetch is LDS.128 / LDS.64:
//   A: [mtile(8)][kstep(4)][lane(32)][reg(4)]   (16 KB per stage)
//   B: [ntile(16)][kstep(4)][lane(32)][reg(2)]  (16 KB per stage)
// Double-buffered: 2 stages x 32 KB = 64 KB dynamic smem.
// ---------------------------------------------------------------------------
#define GEMM_SMEM (2 * 32768)

template<bool BIAS>
__global__ void __launch_bounds__(256, 2)
gemm_mma(const float* __restrict__ A, const float* __restrict__ Bt,
         const float* __restrict__ bias, float* __restrict__ C, int N, int K)
{
    extern __shared__ float sm[];           // [stage(2)][8192]; A first 4096, B next 4096

    const int tid = threadIdx.x;
    const int wid = tid >> 5;
    const int lid = tid & 31;
    const int wr  = wid >> 2;               // 0..1  (M row of warp)
    const int wc  = wid & 3;                // 0..3  (N col of warp)

    const int nchunk = K >> 5;

    const float* Ab = A  + (size_t)(blockIdx.y * 128) * K;
    const float* Bb = Bt + (size_t)(blockIdx.x * 128) * K;

    float acc[4][4][4];
    #pragma unroll
    for (int i = 0; i < 4; i++)
        #pragma unroll
        for (int j = 0; j < 4; j++)
            #pragma unroll
            for (int r = 0; r < 4; r++) acc[i][j][r] = 0.0f;

    // Per-thread load pattern: 4 float4 each from A and B tiles (128 rows x 32 k)
    int rowg[4], kc4[4];
    #pragma unroll
    for (int i = 0; i < 4; i++) {
        int f4 = tid + i * 256;
        rowg[i] = f4 >> 3;
        kc4[i]  = f4 & 7;
    }

    float4 ra[4], rb[4];

    // Fetch chunk c into registers
    auto fetch = [&](int c) {
        #pragma unroll
        for (int i = 0; i < 4; i++) {
            const float* ga = Ab + (size_t)rowg[i] * K + c * 32 + kc4[i] * 4;
            const float* gb = Bb + (size_t)rowg[i] * K + c * 32 + kc4[i] * 4;
            ra[i] = *(const float4*)ga;
            rb[i] = *(const float4*)gb;
        }
    };
    // Store registers into stage s (fragment order), tf32-rounding A
    auto store = [&](int s) {
        float* sA = sm + s * 8192;
        float* sB = sA + 4096;
        #pragma unroll
        for (int i = 0; i < 4; i++) {
            int mt  = rowg[i] >> 4;
            int ks  = kc4[i] >> 1;
            int rgA = ((rowg[i] >> 3) & 1) | ((kc4[i] & 1) << 1);
            float* pa = sA + ((mt * 4 + ks) * 32 + (rowg[i] & 7) * 4) * 4 + rgA;
            pa[0]  = to_tf32(ra[i].x);
            pa[4]  = to_tf32(ra[i].y);
            pa[8]  = to_tf32(ra[i].z);
            pa[12] = to_tf32(ra[i].w);
            int nt  = rowg[i] >> 3;
            int rgB = kc4[i] & 1;
            float* pb = sB + ((nt * 4 + ks) * 32 + (rowg[i] & 7) * 4) * 2 + rgB;
            pb[0] = rb[i].x;
            pb[2] = rb[i].y;
            pb[4] = rb[i].z;
            pb[6] = rb[i].w;
        }
    };

    fetch(0);
    store(0);
    __syncthreads();

    for (int c = 0; c < nchunk; c++) {
        const int cur = c & 1;
        if (c + 1 < nchunk) fetch(c + 1);

        const float* sA = sm + cur * 8192;
        const float* sB = sA + 4096;
        #pragma unroll
        for (int ks = 0; ks < 4; ks++) {
            uint32_t afr[4][4];
            uint32_t bfr[4][2];
            #pragma unroll
            for (int mt = 0; mt < 4; mt++) {
                const float4 v = *(const float4*)(sA + (((wr * 4 + mt) * 4 + ks) * 32 + lid) * 4);
                afr[mt][0] = __float_as_uint(v.x);
                afr[mt][1] = __float_as_uint(v.y);
                afr[mt][2] = __float_as_uint(v.z);
                afr[mt][3] = __float_as_uint(v.w);
            }
            #pragma unroll
            for (int nt = 0; nt < 4; nt++) {
                const float2 v = *(const float2*)(sB + (((wc * 4 + nt) * 4 + ks) * 32 + lid) * 2);
                bfr[nt][0] = __float_as_uint(v.x);
                bfr[nt][1] = __float_as_uint(v.y);
            }
            #pragma unroll
            for (int mt = 0; mt < 4; mt++)
                #pragma unroll
                for (int nt = 0; nt < 4; nt++)
                    mma_tf32(acc[mt][nt], afr[mt], bfr[nt]);
        }

        if (c + 1 < nchunk) {
            store((c + 1) & 1);
            __syncthreads();
        }
    }

    // Epilogue
    const int r0 = blockIdx.y * 128 + wr * 64 + (lid >> 2);
    const int c0 = blockIdx.x * 128 + wc * 32 + (lid & 3) * 2;
    #pragma unroll
    for (int mt = 0; mt < 4; mt++) {
        #pragma unroll
        for (int nt = 0; nt < 4; nt++) {
            int row = r0 + mt * 16;
            int col = c0 + nt * 8;
            float2 v0 = make_float2(acc[mt][nt][0], acc[mt][nt][1]);
            float2 v1 = make_float2(acc[mt][nt][2], acc[mt][nt][3]);
            if (BIAS) {
                float b0 = bias[col], b1 = bias[col + 1];
                v0.x += b0; v0.y += b1;
                v1.x += b0; v1.y += b1;
            }
            *(float2*)(C + (size_t)row * N + col)       = v0;
            *(float2*)(C + (size_t)(row + 8) * N + col) = v1;
        }
    }
}

// ---------------------------------------------------------------------------
// Block-sparse attention (unchanged — passing, ~1/3 of runtime; next target)
// ---------------------------------------------------------------------------
__global__ void __launch_bounds__(256)
attn_kernel(const float* __restrict__ qkv, const void* __restrict__ layout,
            float* __restrict__ att)
{
    const int qb = blockIdx.x;
    const int h  = blockIdx.y;
    const int bz = blockIdx.z;
    const int tid = threadIdx.x;

    __shared__ float qs[16 * 65];
    __shared__ float ks[16 * 65];
    __shared__ float vs[16 * 64];
    __shared__ float ps[16 * 17];
    __shared__ float m_s[16], l_s[16], alpha_s[16];

    const int probe = __ldg(&((const int*)layout)[32]);
    const bool lay_u8 = (probe == 257);
    const unsigned char* lay8 = (const unsigned char*)layout;
    const int* lay32 = (const int*)layout;

    const float scale = 0.125f;

    {
        int idx = tid * 4;
        int i = idx >> 6, d = idx & 63;
        int grow = qb * 16 + i;
        const float* qp = qkv + ((size_t)(bz * SEQ) + grow) * N3 + h * 64 + d;
        float4 q4 = *(const float4*)qp;
        qs[i * 65 + d + 0] = q4.x * scale;
        qs[i * 65 + d + 1] = q4.y * scale;
        qs[i * 65 + d + 2] = q4.z * scale;
        qs[i * 65 + d + 3] = q4.w * scale;
    }
    if (tid < 16) { m_s[tid] = -INFINITY; l_s[tid] = 0.0f; }

    const int orow = tid >> 4;
    const int ocol = (tid & 15) * 4;
    float acc0 = 0.f, acc1 = 0.f, acc2 = 0.f, acc3 = 0.f;

    for (int kb = 0; kb <= qb; kb++) {
        bool allowed = lay_u8 ? (lay8[qb * NB + kb] != 0)
                              : (lay32[qb * NB + kb] != 0);
        if (!allowed) continue;

        __syncthreads();

        {
            int idx = tid * 4;
            int i = idx >> 6, d = idx & 63;
            int grow = kb * 16 + i;
            size_t base = ((size_t)(bz * SEQ) + grow) * N3 + h * 64 + d;
            float4 k4 = *(const float4*)(qkv + base + 1024);
            ks[i * 65 + d + 0] = k4.x;
            ks[i * 65 + d + 1] = k4.y;
            ks[i * 65 + d + 2] = k4.z;
            ks[i * 65 + d + 3] = k4.w;
            *(float4*)(vs + i * 64 + d) = *(const float4*)(qkv + base + 2048);
        }
        __syncthreads();

        {
            int i = tid >> 4, j = tid & 15;
            float s = 0.0f;
            #pragma unroll
            for (int d = 0; d < 64; d++)
                s = fmaf(qs[i * 65 + d], ks[j * 65 + d], s);
            if (kb == qb && j > i) s = -1e30f;
            ps[i * 17 + j] = s;
        }
        __syncthreads();

        if (tid < 16) {
            int i = tid;
            float mo = m_s[i];
            float mx = mo;
            #pragma unroll
            for (int j = 0; j < 16; j++) mx = fmaxf(mx, ps[i * 17 + j]);
            float al = __expf(mo - mx);
            float sum = 0.0f;
            #pragma unroll
            for (int j = 0; j < 16; j++) {
                float e = __expf(ps[i * 17 + j] - mx);
                ps[i * 17 + j] = e;
                sum += e;
            }
            l_s[i] = l_s[i] * al + sum;
            m_s[i] = mx;
            alpha_s[i] = al;
        }
        __syncthreads();

        {
            float al = alpha_s[orow];
            acc0 *= al; acc1 *= al; acc2 *= al; acc3 *= al;
            #pragma unroll
            for (int j = 0; j < 16; j++) {
                float p = ps[orow * 17 + j];
                const float* vr = vs + j * 64 + ocol;
                acc0 = fmaf(p, vr[0], acc0);
                acc1 = fmaf(p, vr[1], acc1);
                acc2 = fmaf(p, vr[2], acc2);
                acc3 = fmaf(p, vr[3], acc3);
            }
        }
    }

    __syncthreads();
    {
        float inv = 1.0f / l_s[orow];
        int grow = qb * 16 + orow;
        float4 o4;
        o4.x = acc0 * inv; o4.y = acc1 * inv; o4.z = acc2 * inv; o4.w = acc3 * inv;
        *(float4*)(att + ((size_t)(bz * SEQ) + grow) * DIM + h * 64 + ocol) = o4;
    }
}

// ---------------------------------------------------------------------------
extern "C" void kernel_launch(void* const* d_in, const int* in_sizes, int n_in,
                              void* d_out, int out_size)
{
    const float* x      = (const float*)d_in[0];
    const float* w_qkv  = (const float*)d_in[1];
    const float* w_out  = (const float*)d_in[2];
    const float* b_out  = (const float*)d_in[3];
    const void*  layout = d_in[4];
    float* out = (float*)d_out;

    void* p;
    cudaGetSymbolAddress(&p, g_qkv);   float* qkv   = (float*)p;
    cudaGetSymbolAddress(&p, g_att);   float* att   = (float*)p;
    cudaGetSymbolAddress(&p, g_wqkvT); float* wqkvT = (float*)p;
    cudaGetSymbolAddress(&p, g_woutT); float* woutT = (float*)p;

    cudaFuncSetAttribute(gemm_mma<false>,
                         cudaFuncAttributeMaxDynamicSharedMemorySize, GEMM_SMEM);
    cudaFuncSetAttribute(gemm_mma<true>,
                         cudaFuncAttributeMaxDynamicSharedMemorySize, GEMM_SMEM);

    // 0) Pre-transpose weights to K-major (+ tf32 rounding)
    transpose_tf32<<<dim3(N3 / 32, DIM / 32), dim3(32, 8)>>>(w_qkv, wqkvT, DIM, N3);
    transpose_tf32<<<dim3(DIM / 32, DIM / 32), dim3(32, 8)>>>(w_out, woutT, DIM, DIM);

    // 1) QKV projection: [4096,1024] @ [1024,3072]
    gemm_mma<false><<<dim3(N3 / 128, MROWS / 128), 256, GEMM_SMEM>>>(
        x, wqkvT, nullptr, qkv, N3, DIM);

    // 2) Block-sparse attention
    attn_kernel<<<dim3(NB, HEADS, BATCH), 256>>>(qkv, layout, att);

    // 3) Output projection + bias
    gemm_mma<true><<<dim3(DIM / 128, MROWS / 128), 256, GEMM_SMEM>>>(
        att, woutT, b_out, out, DIM, DIM);
}

// round 4
// speedup vs baseline: 2.6462x; 1.6974x over previous
#include <cuda_runtime.h>
#include <math.h>
#include <stdint.h>

#define HEADS   16
#define DH      64
#define BLK     16
#define SEQ     2048
#define NB      128
#define BATCH   2
#define DIM     1024
#define N3      3072
#define MROWS   (BATCH * SEQ)   // 4096

// ---------------------------------------------------------------------------
// Scratch (device globals — no allocations anywhere)
// ---------------------------------------------------------------------------
__device__ float g_qkv[(size_t)MROWS * N3];    // 4096 x 3072
__device__ float g_att[(size_t)MROWS * DIM];   // 4096 x 1024
__device__ float g_wqkvT[(size_t)N3 * DIM];    // 3072 x 1024 (K-major, tf32-rounded)
__device__ float g_woutT[(size_t)DIM * DIM];   // 1024 x 1024

__device__ __forceinline__ float to_tf32(float x) {
    uint32_t u;
    asm("cvt.rna.tf32.f32 %0, %1;" : "=r"(u) : "f"(x));
    return __uint_as_float(u);
}

// mma.sync m16n8k8 tf32: D = A*B + D  (fp32 accum)
__device__ __forceinline__ void mma_tf32(float* c, const uint32_t* a, const uint32_t* b) {
    asm volatile(
        "mma.sync.aligned.m16n8k8.row.col.f32.tf32.tf32.f32 "
        "{%0,%1,%2,%3}, {%4,%5,%6,%7}, {%8,%9}, {%0,%1,%2,%3};"
        : "+f"(c[0]), "+f"(c[1]), "+f"(c[2]), "+f"(c[3])
        : "r"(a[0]), "r"(a[1]), "r"(a[2]), "r"(a[3]), "r"(b[0]), "r"(b[1]));
}

// ---------------------------------------------------------------------------
// Transpose + tf32 round: dst[C x R] = tf32(src[R x C])^T
// ---------------------------------------------------------------------------
__global__ void __launch_bounds__(256)
transpose_tf32(const float* __restrict__ src, float* __restrict__ dst, int R, int C)
{
    __shared__ float t[32][33];
    int c0 = blockIdx.x * 32, r0 = blockIdx.y * 32;
    int x = threadIdx.x, y = threadIdx.y;  // block (32, 8)
    #pragma unroll
    for (int i = 0; i < 32; i += 8)
        t[y + i][x] = to_tf32(src[(size_t)(r0 + y + i) * C + c0 + x]);
    __syncthreads();
    #pragma unroll
    for (int i = 0; i < 32; i += 8)
        dst[(size_t)(c0 + y + i) * R + r0 + x] = t[x][y + i];
}

// ---------------------------------------------------------------------------
// mma.sync tf32 GEMM (unchanged from round 3 — proven)
// ---------------------------------------------------------------------------
#define GEMM_SMEM (2 * 32768)

template<bool BIAS>
__global__ void __launch_bounds__(256, 2)
gemm_mma(const float* __restrict__ A, const float* __restrict__ Bt,
         const float* __restrict__ bias, float* __restrict__ C, int N, int K)
{
    extern __shared__ float sm[];

    const int tid = threadIdx.x;
    const int wid = tid >> 5;
    const int lid = tid & 31;
    const int wr  = wid >> 2;
    const int wc  = wid & 3;

    const int nchunk = K >> 5;

    const float* Ab = A  + (size_t)(blockIdx.y * 128) * K;
    const float* Bb = Bt + (size_t)(blockIdx.x * 128) * K;

    float acc[4][4][4];
    #pragma unroll
    for (int i = 0; i < 4; i++)
        #pragma unroll
        for (int j = 0; j < 4; j++)
            #pragma unroll
            for (int r = 0; r < 4; r++) acc[i][j][r] = 0.0f;

    int rowg[4], kc4[4];
    #pragma unroll
    for (int i = 0; i < 4; i++) {
        int f4 = tid + i * 256;
        rowg[i] = f4 >> 3;
        kc4[i]  = f4 & 7;
    }

    float4 ra[4], rb[4];

    auto fetch = [&](int c) {
        #pragma unroll
        for (int i = 0; i < 4; i++) {
            ra[i] = *(const float4*)(Ab + (size_t)rowg[i] * K + c * 32 + kc4[i] * 4);
            rb[i] = *(const float4*)(Bb + (size_t)rowg[i] * K + c * 32 + kc4[i] * 4);
        }
    };
    auto store = [&](int s) {
        float* sA = sm + s * 8192;
        float* sB = sA + 4096;
        #pragma unroll
        for (int i = 0; i < 4; i++) {
            int mt  = rowg[i] >> 4;
            int ks  = kc4[i] >> 1;
            int rgA = ((rowg[i] >> 3) & 1) | ((kc4[i] & 1) << 1);
            float* pa = sA + ((mt * 4 + ks) * 32 + (rowg[i] & 7) * 4) * 4 + rgA;
            pa[0]  = to_tf32(ra[i].x);
            pa[4]  = to_tf32(ra[i].y);
            pa[8]  = to_tf32(ra[i].z);
            pa[12] = to_tf32(ra[i].w);
            int nt  = rowg[i] >> 3;
            int rgB = kc4[i] & 1;
            float* pb = sB + ((nt * 4 + ks) * 32 + (rowg[i] & 7) * 4) * 2 + rgB;
            pb[0] = rb[i].x;
            pb[2] = rb[i].y;
            pb[4] = rb[i].z;
            pb[6] = rb[i].w;
        }
    };

    fetch(0);
    store(0);
    __syncthreads();

    for (int c = 0; c < nchunk; c++) {
        const int cur = c & 1;
        if (c + 1 < nchunk) fetch(c + 1);

        const float* sA = sm + cur * 8192;
        const float* sB = sA + 4096;
        #pragma unroll
        for (int ks = 0; ks < 4; ks++) {
            uint32_t afr[4][4];
            uint32_t bfr[4][2];
            #pragma unroll
            for (int mt = 0; mt < 4; mt++) {
                const float4 v = *(const float4*)(sA + (((wr * 4 + mt) * 4 + ks) * 32 + lid) * 4);
                afr[mt][0] = __float_as_uint(v.x);
                afr[mt][1] = __float_as_uint(v.y);
                afr[mt][2] = __float_as_uint(v.z);
                afr[mt][3] = __float_as_uint(v.w);
            }
            #pragma unroll
            for (int nt = 0; nt < 4; nt++) {
                const float2 v = *(const float2*)(sB + (((wc * 4 + nt) * 4 + ks) * 32 + lid) * 2);
                bfr[nt][0] = __float_as_uint(v.x);
                bfr[nt][1] = __float_as_uint(v.y);
            }
            #pragma unroll
            for (int mt = 0; mt < 4; mt++)
                #pragma unroll
                for (int nt = 0; nt < 4; nt++)
                    mma_tf32(acc[mt][nt], afr[mt], bfr[nt]);
        }

        if (c + 1 < nchunk) {
            store((c + 1) & 1);
            __syncthreads();
        }
    }

    const int r0 = blockIdx.y * 128 + wr * 64 + (lid >> 2);
    const int c0 = blockIdx.x * 128 + wc * 32 + (lid & 3) * 2;
    #pragma unroll
    for (int mt = 0; mt < 4; mt++) {
        #pragma unroll
        for (int nt = 0; nt < 4; nt++) {
            int row = r0 + mt * 16;
            int col = c0 + nt * 8;
            float2 v0 = make_float2(acc[mt][nt][0], acc[mt][nt][1]);
            float2 v1 = make_float2(acc[mt][nt][2], acc[mt][nt][3]);
            if (BIAS) {
                float b0 = bias[col], b1 = bias[col + 1];
                v0.x += b0; v0.y += b1;
                v1.x += b0; v1.y += b1;
            }
            *(float2*)(C + (size_t)row * N + col)       = v0;
            *(float2*)(C + (size_t)(row + 8) * N + col) = v1;
        }
    }
}

// ---------------------------------------------------------------------------
// mma.sync flash attention, warp-split-K over allowed key blocks.
// CTA = 128 threads (4 warps) per (qb, h, bz). Each warp owns every 4th
// allowed key block with private online-softmax state; combined at the end.
//
// Per-warp smem region wbuf[w] (2464 floats):
//   K tile:  [0, 1088)   16 rows x stride 68 (conflict-free B-frag loads)
//   V tile:  [1088, 2176) 16 x 68
//   P tile:  [2176, 2464) 16 x stride 18
// Epilogue reuse of the same region:
//   O part:  [0, 1056)   16 x stride 66
//   m[16]:   [1056, 1072),  l[16]: [1072, 1088)
// ---------------------------------------------------------------------------
__global__ void __launch_bounds__(128)
attn_mma(const float* __restrict__ qkv, const void* __restrict__ layout,
         float* __restrict__ att)
{
    __shared__ __align__(16) float wbuf[4][2464];
    __shared__ int list[NB];
    __shared__ int wcnt[4];

    const int qb = blockIdx.x, h = blockIdx.y, bz = blockIdx.z;
    const int tid = threadIdx.x;
    const int wid = tid >> 5;
    const int lid = tid & 31;
    const int r4  = lid >> 2;     // 0..7
    const int c4  = lid & 3;      // 0..3

    // ---- build allowed-block list (ballot compaction) ----
    const int probe = __ldg(&((const int*)layout)[32]);
    const bool u8 = (probe == 257);
    const int kb0 = wid * 32 + lid;
    bool ok = (kb0 <= qb) &&
              (u8 ? (((const unsigned char*)layout)[qb * NB + kb0] != 0)
                  : (((const int*)layout)[qb * NB + kb0] != 0));
    unsigned bmask = __ballot_sync(0xffffffffu, ok);
    if (lid == 0) wcnt[wid] = __popc(bmask);
    __syncthreads();
    int pre = 0;
    #pragma unroll
    for (int w = 0; w < 4; w++) pre += (w < wid) ? wcnt[w] : 0;
    const int total = wcnt[0] + wcnt[1] + wcnt[2] + wcnt[3];
    if (ok) list[pre + __popc(bmask & ((1u << lid) - 1u))] = kb0;
    __syncthreads();

    // ---- Q fragments (loaded once, pre-scaled, tf32) ----
    const float scale = 0.125f;
    const float* qp = qkv + (size_t)(bz * SEQ + qb * 16) * N3 + h * 64;
    uint32_t qa[8][4];
    #pragma unroll
    for (int ks = 0; ks < 8; ks++) {
        qa[ks][0] = __float_as_uint(to_tf32(qp[(size_t)r4 * N3       + ks * 8 + c4]     * scale));
        qa[ks][1] = __float_as_uint(to_tf32(qp[(size_t)(r4 + 8) * N3 + ks * 8 + c4]     * scale));
        qa[ks][2] = __float_as_uint(to_tf32(qp[(size_t)r4 * N3       + ks * 8 + c4 + 4] * scale));
        qa[ks][3] = __float_as_uint(to_tf32(qp[(size_t)(r4 + 8) * N3 + ks * 8 + c4 + 4] * scale));
    }

    float o[8][4];
    #pragma unroll
    for (int nt = 0; nt < 8; nt++)
        #pragma unroll
        for (int r = 0; r < 4; r++) o[nt][r] = 0.0f;
    float m_lo = -INFINITY, m_hi = -INFINITY, l_lo = 0.0f, l_hi = 0.0f;

    float* Ks = wbuf[wid];
    float* Vs = Ks + 1088;
    float* Ps = Ks + 2176;

    for (int it = wid; it < total; it += 4) {
        const int kb = list[it];
        const float* kvb = qkv + (size_t)(bz * SEQ + kb * 16) * N3 + h * 64;

        // stage K, V (tf32-rounded), 8 float4 each per lane
        #pragma unroll
        for (int j = 0; j < 8; j++) {
            int f = lid + j * 32;         // 0..255
            int row = f >> 4, c16 = f & 15;
            float4 k4 = *(const float4*)(kvb + (size_t)row * N3 + 1024 + c16 * 4);
            float* kd = Ks + row * 68 + c16 * 4;
            kd[0] = to_tf32(k4.x); kd[1] = to_tf32(k4.y);
            kd[2] = to_tf32(k4.z); kd[3] = to_tf32(k4.w);
            float4 v4 = *(const float4*)(kvb + (size_t)row * N3 + 2048 + c16 * 4);
            float* vd = Vs + row * 68 + c16 * 4;
            vd[0] = to_tf32(v4.x); vd[1] = to_tf32(v4.y);
            vd[2] = to_tf32(v4.z); vd[3] = to_tf32(v4.w);
        }
        __syncwarp();

        // S = Q @ K^T  (two n-tiles of 8 keys)
        float s0[4] = {0.f, 0.f, 0.f, 0.f};
        float s1[4] = {0.f, 0.f, 0.f, 0.f};
        #pragma unroll
        for (int ks = 0; ks < 8; ks++) {
            uint32_t b0[2], b1[2];
            b0[0] = __float_as_uint(Ks[r4 * 68 + ks * 8 + c4]);
            b0[1] = __float_as_uint(Ks[r4 * 68 + ks * 8 + c4 + 4]);
            b1[0] = __float_as_uint(Ks[(8 + r4) * 68 + ks * 8 + c4]);
            b1[1] = __float_as_uint(Ks[(8 + r4) * 68 + ks * 8 + c4 + 4]);
            mma_tf32(s0, qa[ks], b0);
            mma_tf32(s1, qa[ks], b1);
        }

        // causal mask inside diagonal block
        if (kb == qb) {
            const int cA = 2 * c4, cB = 2 * c4 + 1;
            if (cA > r4)     s0[0] = -1e30f;
            if (cB > r4)     s0[1] = -1e30f;
            if (cA > r4 + 8) s0[2] = -1e30f;
            if (cB > r4 + 8) s0[3] = -1e30f;
            if (cA + 8 > r4)     s1[0] = -1e30f;
            if (cB + 8 > r4)     s1[1] = -1e30f;
            if (cA + 8 > r4 + 8) s1[2] = -1e30f;
            if (cB + 8 > r4 + 8) s1[3] = -1e30f;
        }

        // row max (quad butterfly)
        float lo = fmaxf(fmaxf(s0[0], s0[1]), fmaxf(s1[0], s1[1]));
        float hi = fmaxf(fmaxf(s0[2], s0[3]), fmaxf(s1[2], s1[3]));
        lo = fmaxf(lo, __shfl_xor_sync(0xffffffffu, lo, 1));
        lo = fmaxf(lo, __shfl_xor_sync(0xffffffffu, lo, 2));
        hi = fmaxf(hi, __shfl_xor_sync(0xffffffffu, hi, 1));
        hi = fmaxf(hi, __shfl_xor_sync(0xffffffffu, hi, 2));

        const float mlo = fmaxf(m_lo, lo);
        const float mhi = fmaxf(m_hi, hi);
        const float alo = __expf(m_lo - mlo);
        const float ahi = __expf(m_hi - mhi);

        float p00 = __expf(s0[0] - mlo), p01 = __expf(s0[1] - mlo);
        float p10 = __expf(s1[0] - mlo), p11 = __expf(s1[1] - mlo);
        float p02 = __expf(s0[2] - mhi), p03 = __expf(s0[3] - mhi);
        float p12 = __expf(s1[2] - mhi), p13 = __expf(s1[3] - mhi);

        float slo = p00 + p01 + p10 + p11;
        float shi = p02 + p03 + p12 + p13;
        slo += __shfl_xor_sync(0xffffffffu, slo, 1);
        slo += __shfl_xor_sync(0xffffffffu, slo, 2);
        shi += __shfl_xor_sync(0xffffffffu, shi, 1);
        shi += __shfl_xor_sync(0xffffffffu, shi, 2);

        l_lo = l_lo * alo + slo;
        l_hi = l_hi * ahi + shi;
        m_lo = mlo; m_hi = mhi;

        // rescale O
        #pragma unroll
        for (int nt = 0; nt < 8; nt++) {
            o[nt][0] *= alo; o[nt][1] *= alo;
            o[nt][2] *= ahi; o[nt][3] *= ahi;
        }

        // store P (tf32) to smem in C-frag layout
        *(float2*)&Ps[r4 * 18 + 2 * c4]           = make_float2(to_tf32(p00), to_tf32(p01));
        *(float2*)&Ps[r4 * 18 + 8 + 2 * c4]       = make_float2(to_tf32(p10), to_tf32(p11));
        *(float2*)&Ps[(r4 + 8) * 18 + 2 * c4]     = make_float2(to_tf32(p02), to_tf32(p03));
        *(float2*)&Ps[(r4 + 8) * 18 + 8 + 2 * c4] = make_float2(to_tf32(p12), to_tf32(p13));
        __syncwarp();

        // P as A fragments (2 k-steps over 16 keys)
        uint32_t pa0[4], pa1[4];
        pa0[0] = __float_as_uint(Ps[r4 * 18 + c4]);
        pa0[1] = __float_as_uint(Ps[(r4 + 8) * 18 + c4]);
        pa0[2] = __float_as_uint(Ps[r4 * 18 + c4 + 4]);
        pa0[3] = __float_as_uint(Ps[(r4 + 8) * 18 + c4 + 4]);
        pa1[0] = __float_as_uint(Ps[r4 * 18 + 8 + c4]);
        pa1[1] = __float_as_uint(Ps[(r4 + 8) * 18 + 8 + c4]);
        pa1[2] = __float_as_uint(Ps[r4 * 18 + 8 + c4 + 4]);
        pa1[3] = __float_as_uint(Ps[(r4 + 8) * 18 + 8 + c4 + 4]);

        // O += P @ V   (8 n-tiles over d=64)
        #pragma unroll
        for (int nt = 0; nt < 8; nt++) {
            uint32_t b0[2], b1[2];
            b0[0] = __float_as_uint(Vs[c4 * 68 + nt * 8 + r4]);
            b0[1] = __float_as_uint(Vs[(c4 + 4) * 68 + nt * 8 + r4]);
            mma_tf32(o[nt], pa0, b0);
            b1[0] = __float_as_uint(Vs[(8 + c4) * 68 + nt * 8 + r4]);
            b1[1] = __float_as_uint(Vs[(12 + c4) * 68 + nt * 8 + r4]);
            mma_tf32(o[nt], pa1, b1);
        }
        __syncwarp();
    }

    // ---- write per-warp partials (reuse K region) ----
    float* Os = wbuf[wid];
    #pragma unroll
    for (int nt = 0; nt < 8; nt++) {
        *(float2*)&Os[r4 * 66 + nt * 8 + 2 * c4]       = make_float2(o[nt][0], o[nt][1]);
        *(float2*)&Os[(r4 + 8) * 66 + nt * 8 + 2 * c4] = make_float2(o[nt][2], o[nt][3]);
    }
    if (c4 == 0) {
        Os[1056 + r4]     = m_lo;
        Os[1056 + 8 + r4] = m_hi;
        Os[1072 + r4]     = l_lo;
        Os[1072 + 8 + r4] = l_hi;
    }
    __syncthreads();

    // ---- split-K combine: 128 threads over 16 rows x 64 d ----
    {
        const int row = tid >> 3;
        const int d0  = (tid & 7) * 8;
        float mw[4], lw[4];
        float M = -INFINITY;
        #pragma unroll
        for (int w = 0; w < 4; w++) {
            mw[w] = wbuf[w][1056 + row];
            lw[w] = wbuf[w][1072 + row];
            M = fmaxf(M, mw[w]);
        }
        float L = 0.0f, wgt[4];
        #pragma unroll
        for (int w = 0; w < 4; w++) {
            wgt[w] = __expf(mw[w] - M);
            L += wgt[w] * lw[w];
        }
        const float inv = 1.0f / L;
        float out[8];
        #pragma unroll
        for (int j = 0; j < 8; j++) out[j] = 0.0f;
        #pragma unroll
        for (int w = 0; w < 4; w++) {
            const float g = wgt[w];
            const float* op = &wbuf[w][row * 66 + d0];
            #pragma unroll
            for (int j = 0; j < 8; j++) out[j] += g * op[j];
        }
        float* ap = att + (size_t)(bz * SEQ + qb * 16 + row) * DIM + h * 64 + d0;
        float4 v0 = make_float4(out[0] * inv, out[1] * inv, out[2] * inv, out[3] * inv);
        float4 v1 = make_float4(out[4] * inv, out[5] * inv, out[6] * inv, out[7] * inv);
        *(float4*)(ap)     = v0;
        *(float4*)(ap + 4) = v1;
    }
}

// ---------------------------------------------------------------------------
extern "C" void kernel_launch(void* const* d_in, const int* in_sizes, int n_in,
                              void* d_out, int out_size)
{
    const float* x      = (const float*)d_in[0];
    const float* w_qkv  = (const float*)d_in[1];
    const float* w_out  = (const float*)d_in[2];
    const float* b_out  = (const float*)d_in[3];
    const void*  layout = d_in[4];
    float* out = (float*)d_out;

    void* p;
    cudaGetSymbolAddress(&p, g_qkv);   float* qkv   = (float*)p;
    cudaGetSymbolAddress(&p, g_att);   float* att   = (float*)p;
    cudaGetSymbolAddress(&p, g_wqkvT); float* wqkvT = (float*)p;
    cudaGetSymbolAddress(&p, g_woutT); float* woutT = (float*)p;

    cudaFuncSetAttribute(gemm_mma<false>,
                         cudaFuncAttributeMaxDynamicSharedMemorySize, GEMM_SMEM);
    cudaFuncSetAttribute(gemm_mma<true>,
                         cudaFuncAttributeMaxDynamicSharedMemorySize, GEMM_SMEM);

    // 0) Pre-transpose weights to K-major (+ tf32 rounding)
    transpose_tf32<<<dim3(N3 / 32, DIM / 32), dim3(32, 8)>>>(w_qkv, wqkvT, DIM, N3);
    transpose_tf32<<<dim3(DIM / 32, DIM / 32), dim3(32, 8)>>>(w_out, woutT, DIM, DIM);

    // 1) QKV projection: [4096,1024] @ [1024,3072]
    gemm_mma<false><<<dim3(N3 / 128, MROWS / 128), 256, GEMM_SMEM>>>(
        x, wqkvT, nullptr, qkv, N3, DIM);

    // 2) Block-sparse flash attention (mma.sync)
    attn_mma<<<dim3(NB, HEADS, BATCH), 128>>>(qkv, layout, att);

    // 3) Output projection + bias
    gemm_mma<true><<<dim3(DIM / 128, MROWS / 128), 256, GEMM_SMEM>>>(
        att, woutT, b_out, out, DIM, DIM);
}